// round 11
// baseline (speedup 1.0000x reference)
#include <cuda_runtime.h>

#define N_BOX    1024
#define N_CLS    80
#define MAX_OUT  100
#define THREADS  512
#define CAP      640              // bitmask matrix row capacity (cutoff ~512 expected)
#define MW       ((CAP + 31)/32)  // 20 words per row

// Inter-block channel within ONE launch (proven working in round 10).
__device__ int g_res[N_CLS * MAX_OUT];
__device__ int g_cnt[N_CLS];
__device__ int g_done;   // zero at load; block 0 resets it each launch

// Dynamic smem layout: keys[1024] (8192B) | y1,x1,y2,x2,area[1024] (20480B)
// | mask[CAP*MW] (51200B)  => 79872 bytes
#define DYN_BYTES (8192 + 20480 + 51200)

__global__ __launch_bounds__(THREADS) void nms_fused(
    const float* __restrict__ boxes,   // [N_BOX, 4] (y1,x1,y2,x2)
    const float* __restrict__ scores,  // [N_CLS, N_BOX]
    float*       __restrict__ out,     // [out_size] float32 (!)
    int out_size)
{
    const int c   = blockIdx.x;
    const int tid = threadIdx.x;

    extern __shared__ unsigned char dyn[];
    unsigned long long* keys = (unsigned long long*)dyn;
    float* y1s = (float*)(dyn + 8192);
    float* x1s = y1s + N_BOX;
    float* y2s = x1s + N_BOX;
    float* x2s = y2s + N_BOX;
    float* ars = x2s + N_BOX;
    unsigned int* mask = (unsigned int*)(dyn + 8192 + 20480);

    __shared__ int res_s[MAX_OUT];
    __shared__ int s_cut;
    __shared__ int s_rank;

    // Zero this block's slice of the output (block 0 scatters later, strictly
    // after all blocks arrive, so ordering is covered by the fence+atomic).
    for (int i = c * THREADS + tid; i < out_size; i += N_CLS * THREADS)
        out[i] = 0.0f;

    // ---- composite keys: ascending == (score desc, index asc) ----
    const float* sc = scores + (size_t)c * N_BOX;
    for (int t = tid; t < N_BOX; t += THREADS) {
        unsigned int bits = __float_as_uint(sc[t]);
        keys[t] = ((unsigned long long)(~bits) << 32) | (unsigned int)t;
    }
    if (tid == 0) { s_cut = 0; s_rank = 0; }
    __syncthreads();

    // ---- bitonic sort ascending (keys unique) ----
    for (int k = 2; k <= N_BOX; k <<= 1) {
        for (int j = k >> 1; j > 0; j >>= 1) {
            for (int t = tid; t < N_BOX; t += THREADS) {
                int ixj = t ^ j;
                if (ixj > t) {
                    bool up = ((t & k) == 0);
                    unsigned long long a = keys[t], b = keys[ixj];
                    if ((a > b) == up) { keys[t] = b; keys[ixj] = a; }
                }
            }
            __syncthreads();
        }
    }

    // ---- cutoff: number of boxes with score > 0.5 (a sorted prefix) ----
    for (int t = tid; t < N_BOX; t += THREADS) {
        float s  = __uint_as_float(~(unsigned int)(keys[t] >> 32));
        bool kt  = (s > 0.5f);
        bool kt1 = false;
        if (t < N_BOX - 1) {
            float s1 = __uint_as_float(~(unsigned int)(keys[t + 1] >> 32));
            kt1 = (s1 > 0.5f);
        }
        if (kt && !kt1) s_cut = t + 1;
        if (t == N_BOX - 1 && kt) s_cut = N_BOX;
    }
    __syncthreads();
    const int cutoff = s_cut;

    // ---- gather boxes (sorted order) for the active prefix ----
    for (int t = tid; t < cutoff; t += THREADS) {
        int o = (int)(keys[t] & 0xFFFFFFFFull);
        float y1 = boxes[4*o+0], x1 = boxes[4*o+1];
        float y2 = boxes[4*o+2], x2 = boxes[4*o+3];
        y1s[t] = y1; x1s[t] = x1; y2s[t] = y2; x2s[t] = x2;
        ars[t] = __fmul_rn(__fsub_rn(y2, y1), __fsub_rn(x2, x1));
    }
    __syncthreads();

    if (cutoff <= CAP) {
        // ---- FAST PATH: parallel suppression bitmask, serial bit greedy ----
        const int nw = (cutoff + 31) >> 5;
        for (int t = tid; t < cutoff * nw; t += THREADS) {
            int i = t / nw, w = t - i * nw;
            unsigned int bits = 0;
            if (w * 32 + 31 > i) {   // word holds some j > i
                const float y1i = y1s[i], x1i = x1s[i];
                const float y2i = y2s[i], x2i = x2s[i];
                const float ai  = ars[i];
                int jbase = w * 32;
                int jend  = min(32, cutoff - jbase);
                for (int b = 0; b < jend; ++b) {
                    int j = jbase + b;
                    if (j > i) {
                        float ih = fmaxf(__fsub_rn(fminf(y2i, y2s[j]),
                                                   fmaxf(y1i, y1s[j])), 0.0f);
                        float iw = fmaxf(__fsub_rn(fminf(x2i, x2s[j]),
                                                   fmaxf(x1i, x1s[j])), 0.0f);
                        float inter = __fmul_rn(ih, iw);
                        float uni   = __fsub_rn(__fadd_rn(ai, ars[j]), inter);
                        // inter==0: iou is 0 or NaN(0/0) -> both fail >0.5,
                        // exactly like the reference.
                        if (inter > 0.0f &&
                            __fdiv_rn(inter, uni) > 0.5f) bits |= 1u << b;
                    }
                }
            }
            mask[(size_t)i * MW + w] = bits;
        }
        __syncthreads();

        // Serial greedy over live-bit words: visits ONLY kept items
        // (a live bit means "not suppressed by any earlier kept" == keep[i]).
        if (tid == 0) {
            unsigned int kw[MW];
            for (int w = 0; w < nw; ++w) {
                int rem = cutoff - w * 32;
                kw[w] = (rem >= 32) ? 0xFFFFFFFFu : ((1u << rem) - 1u);
            }
            int rank = 0;
            for (int w = 0; w < nw && rank < MAX_OUT; ++w) {
                unsigned int live = kw[w];
                while (live && rank < MAX_OUT) {
                    int b = __ffs(live) - 1;
                    int i = w * 32 + b;
                    res_s[rank++] = (int)(keys[i] & 0xFFFFFFFFull);
                    const unsigned int* row = mask + (size_t)i * MW;
                    live &= ~(1u << b);
                    live &= ~row[w];           // suppress j>i in this word
                    for (int w2 = w + 1; w2 < nw; ++w2)
                        kw[w2] &= ~row[w2];
                }
            }
            s_rank = rank;
        }
        __syncthreads();
    } else {
        // ---- FALLBACK (cutoff > CAP; astronomically rare): barrier greedy --
        unsigned char* keepb = (unsigned char*)mask;   // reuse matrix space
        for (int t = tid; t < cutoff; t += THREADS) keepb[t] = 1;
        __syncthreads();
        int rank = 0;
        for (int i = 0; i < cutoff && rank < MAX_OUT; ++i) {
            if (keepb[i]) {
                const float y1i = y1s[i], x1i = x1s[i];
                const float y2i = y2s[i], x2i = x2s[i];
                const float ai  = ars[i];
                for (int j = i + 1 + tid; j < cutoff; j += THREADS) {
                    if (keepb[j]) {
                        float ih = fmaxf(__fsub_rn(fminf(y2i, y2s[j]),
                                                   fmaxf(y1i, y1s[j])), 0.0f);
                        float iw = fmaxf(__fsub_rn(fminf(x2i, x2s[j]),
                                                   fmaxf(x1i, x1s[j])), 0.0f);
                        float inter = __fmul_rn(ih, iw);
                        float uni   = __fsub_rn(__fadd_rn(ai, ars[j]), inter);
                        if (__fdiv_rn(inter, uni) > 0.5f) keepb[j] = 0;
                    }
                }
                if (tid == 0) res_s[rank] = (int)(keys[i] & 0xFFFFFFFFull);
                rank++;
            }
            __syncthreads();
        }
        if (tid == 0) s_rank = rank;
        __syncthreads();
    }

    // ---- publish per-class results; release; arrive ----
    const int rank = s_rank;
    for (int t = tid; t < rank; t += THREADS)
        g_res[c * MAX_OUT + t] = res_s[t];
    if (tid == 0) g_cnt[c] = rank;
    __threadfence();
    __syncthreads();
    if (tid == 0) atomicAdd(&g_done, 1);

    // ---- block 0: wait for all classes, scatter compacted float rows ----
    if (c == 0) {
        if (tid == 0) {
            while (atomicAdd(&g_done, 0) < N_CLS) __nanosleep(100);
        }
        __syncthreads();
        __threadfence();   // acquire before reading g_res/g_cnt

        __shared__ int offs[N_CLS];
        if (tid == 0) {
            int acc = 0;
            for (int cc = 0; cc < N_CLS; ++cc) { offs[cc] = acc; acc += g_cnt[cc]; }
        }
        __syncthreads();

        for (int e = tid; e < N_CLS * MAX_OUT; e += THREADS) {
            int cc = e / MAX_OUT;
            int k  = e - cc * MAX_OUT;
            if (k < g_cnt[cc]) {
                int p = offs[cc] + k;
                out[3 * p + 0] = 0.0f;             // batch (B == 1)
                out[3 * p + 1] = (float)cc;
                out[3 * p + 2] = (float)g_res[e];
            }
        }
        __syncthreads();
        if (tid == 0) { __threadfence(); g_done = 0; }   // reset for replay
    }
}

extern "C" void kernel_launch(void* const* d_in, const int* in_sizes, int n_in,
                              void* d_out, int out_size)
{
    const float* boxes  = (const float*)d_in[0];
    const float* scores = (const float*)(n_in > 1 ? d_in[1] : d_in[0]);
    if (n_in > 1 && in_sizes[0] > in_sizes[1]) {   // clearly reversed
        const float* t = boxes; boxes = scores; scores = t;
    }

    static int attr_set = 0;
    if (!attr_set) {
        cudaFuncSetAttribute(nms_fused,
                             cudaFuncAttributeMaxDynamicSharedMemorySize,
                             DYN_BYTES);
        attr_set = 1;
    }

    nms_fused<<<N_CLS, THREADS, DYN_BYTES>>>(boxes, scores,
                                             (float*)d_out, out_size);
}

// round 12
// speedup vs baseline: 1.0266x; 1.0266x over previous
#include <cuda_runtime.h>

#define N_BOX    1024
#define N_CLS    80
#define MAX_OUT  100
#define THREADS  512
#define CAP      640   // warp-greedy capacity; cutoff~Binom(1024,.5) => 640 = +8 sigma
#define CPL      20    // candidates per lane (CAP/32)

__device__ int g_res[N_CLS * MAX_OUT];
__device__ int g_cnt[N_CLS];

// One block per class: block-wide bitonic argsort, then a ZERO-BARRIER
// warp-ballot greedy with register-resident liveness bits.
__global__ __launch_bounds__(THREADS) void nms_kernel(
    const float4* __restrict__ boxes,   // [N_BOX] (y1,x1,y2,x2)
    const float*  __restrict__ scores,  // [N_CLS, N_BOX]
    float*        __restrict__ out,     // float32 output (zeroed here)
    int out_size)
{
    const int c   = blockIdx.x;
    const int tid = threadIdx.x;

    __shared__ unsigned long long keys[N_BOX];
    __shared__ float4 b4s[N_BOX];
    __shared__ float  ars[N_BOX];
    __shared__ int    res_s[MAX_OUT];
    __shared__ int    s_cut, s_rank;
    __shared__ unsigned char keepb[N_BOX];   // fallback path only

    // Zero the output, spread across all 80 blocks (kernel 2 scatters later).
    {
        int i = c * THREADS + tid;
        if (i < out_size) out[i] = 0.0f;
    }

    // ---- composite keys: ascending == (score desc, index asc) ----
    const float* sc = scores + (size_t)c * N_BOX;
    for (int t = tid; t < N_BOX; t += THREADS) {
        unsigned int bits = __float_as_uint(sc[t]);
        keys[t] = ((unsigned long long)(~bits) << 32) | (unsigned int)t;
    }
    if (tid == 0) { s_cut = 0; s_rank = 0; }
    __syncthreads();

    // ---- bitonic sort ascending (keys unique: index in low bits) ----
    for (int k = 2; k <= N_BOX; k <<= 1) {
        for (int j = k >> 1; j > 0; j >>= 1) {
            for (int t = tid; t < N_BOX; t += THREADS) {
                int ixj = t ^ j;
                if (ixj > t) {
                    bool up = ((t & k) == 0);
                    unsigned long long a = keys[t], b = keys[ixj];
                    if ((a > b) == up) { keys[t] = b; keys[ixj] = a; }
                }
            }
            __syncthreads();
        }
    }

    // ---- cutoff = #scores > 0.5 (a prefix of the sorted order) ----
    for (int t = tid; t < N_BOX; t += THREADS) {
        float s  = __uint_as_float(~(unsigned int)(keys[t] >> 32));
        bool kt  = (s > 0.5f);
        bool kt1 = false;
        if (t < N_BOX - 1) {
            float s1 = __uint_as_float(~(unsigned int)(keys[t + 1] >> 32));
            kt1 = (s1 > 0.5f);
        }
        if (kt && !kt1) s_cut = t + 1;
        if (t == N_BOX - 1 && kt) s_cut = N_BOX;
    }
    __syncthreads();
    const int cutoff = s_cut;

    // ---- gather boxes (sorted order) for the active prefix ----
    for (int t = tid; t < cutoff; t += THREADS) {
        int o = (int)(keys[t] & 0xFFFFFFFFull);
        float4 b = boxes[o];               // (y1,x1,y2,x2)
        b4s[t] = b;
        ars[t] = __fmul_rn(__fsub_rn(b.z, b.x), __fsub_rn(b.w, b.y));
    }
    __syncthreads();

    if (cutoff <= CAP) {
        // ==== FAST PATH: warp 0 greedy, liveness in registers, no barriers ==
        if (tid < 32) {
            const int lane = tid;
            const int base = lane * CPL;
            unsigned int live = 0;
            #pragma unroll
            for (int b = 0; b < CPL; ++b)
                if (base + b < cutoff) live |= 1u << b;

            int rank = 0;
            while (rank < MAX_OUT) {
                unsigned int hs = __ballot_sync(0xFFFFFFFFu, live != 0);
                if (!hs) break;
                int src = __ffs(hs) - 1;           // lowest lane with live bits
                int myi = base + __ffs(live) - 1;  // my lowest live index
                int i   = __shfl_sync(0xFFFFFFFFu, myi, src);  // global min

                if (lane == src) {
                    res_s[rank] = (int)(keys[i] & 0xFFFFFFFFull);
                    live &= live - 1;              // clear bit of i
                }
                rank++;
                if (rank >= MAX_OUT) break;

                float4 bi = b4s[i];                // broadcast smem read
                float  ai = ars[i];
                // All remaining live indices are > i by construction.
                unsigned int m = live;
                while (m) {
                    int bb = __ffs(m) - 1; m &= m - 1;
                    int j = base + bb;
                    float4 bj = b4s[j];
                    float ih = fmaxf(__fsub_rn(fminf(bi.z, bj.z),
                                               fmaxf(bi.x, bj.x)), 0.0f);
                    float iw = fmaxf(__fsub_rn(fminf(bi.w, bj.w),
                                               fmaxf(bi.y, bj.y)), 0.0f);
                    float inter = __fmul_rn(ih, iw);
                    float uni   = __fsub_rn(__fadd_rn(ai, ars[j]), inter);
                    // NaN (0/0) > 0.5 is false, matching the reference.
                    if (__fdiv_rn(inter, uni) > 0.5f) live &= ~(1u << bb);
                }
            }
            if (lane == 0) s_rank = rank;
        }
        __syncthreads();
    } else {
        // ==== FALLBACK (cutoff > CAP, ~1e-15): proven barrier greedy ========
        for (int t = tid; t < cutoff; t += THREADS) keepb[t] = 1;
        __syncthreads();
        int rank = 0;
        for (int i = 0; i < cutoff && rank < MAX_OUT; ++i) {
            if (keepb[i]) {
                float4 bi = b4s[i];
                float  ai = ars[i];
                for (int j = i + 1 + tid; j < cutoff; j += THREADS) {
                    if (keepb[j]) {
                        float4 bj = b4s[j];
                        float ih = fmaxf(__fsub_rn(fminf(bi.z, bj.z),
                                                   fmaxf(bi.x, bj.x)), 0.0f);
                        float iw = fmaxf(__fsub_rn(fminf(bi.w, bj.w),
                                                   fmaxf(bi.y, bj.y)), 0.0f);
                        float inter = __fmul_rn(ih, iw);
                        float uni   = __fsub_rn(__fadd_rn(ai, ars[j]), inter);
                        if (__fdiv_rn(inter, uni) > 0.5f) keepb[j] = 0;
                    }
                }
                if (tid == 0) res_s[rank] = (int)(keys[i] & 0xFFFFFFFFull);
                rank++;
            }
            __syncthreads();
        }
        if (tid == 0) s_rank = rank;
        __syncthreads();
    }

    const int rank = s_rank;
    for (int t = tid; t < rank; t += THREADS)
        g_res[c * MAX_OUT + t] = res_s[t];
    if (tid == 0) g_cnt[c] = rank;
}

// Finalize: counts loaded in PARALLEL (one memory latency, not an 80-deep
// serial global chain), smem scan, compacted float scatter.
__global__ __launch_bounds__(256) void finalize_kernel(float* __restrict__ out)
{
    __shared__ int s_cnt[N_CLS];
    __shared__ int offs[N_CLS];
    const int tid = threadIdx.x;

    if (tid < N_CLS) s_cnt[tid] = g_cnt[tid];
    __syncthreads();
    if (tid == 0) {
        int acc = 0;
        #pragma unroll 8
        for (int c = 0; c < N_CLS; ++c) { offs[c] = acc; acc += s_cnt[c]; }
    }
    __syncthreads();

    for (int e = tid; e < N_CLS * MAX_OUT; e += 256) {
        int c = e / MAX_OUT;
        int k = e - c * MAX_OUT;
        if (k < s_cnt[c]) {
            int p = offs[c] + k;
            out[3 * p + 0] = 0.0f;          // batch index (B == 1)
            out[3 * p + 1] = (float)c;
            out[3 * p + 2] = (float)g_res[e];
        }
    }
}

extern "C" void kernel_launch(void* const* d_in, const int* in_sizes, int n_in,
                              void* d_out, int out_size)
{
    const float* boxes  = (const float*)d_in[0];
    const float* scores = (const float*)(n_in > 1 ? d_in[1] : d_in[0]);
    if (n_in > 1 && in_sizes[0] > in_sizes[1]) {   // clearly reversed
        const float* t = boxes; boxes = scores; scores = t;
    }

    nms_kernel<<<N_CLS, THREADS>>>((const float4*)boxes, scores,
                                   (float*)d_out, out_size);
    finalize_kernel<<<1, 256>>>((float*)d_out);
}

// round 13
// speedup vs baseline: 5.1881x; 5.0536x over previous
#include <cuda_runtime.h>

#define N_BOX    1024
#define N_CLS    80
#define MAX_OUT  100
#define THREADS  512
#define LIVE_INF 0x7FFFFFFF

__device__ int g_res[N_CLS * MAX_OUT];
__device__ int g_cnt[N_CLS];
__device__ int g_done;   // zero at load; block 0 resets each launch

__global__ __launch_bounds__(THREADS) void nms_fused(
    const float4* __restrict__ boxes,   // [N_BOX] (y1,x1,y2,x2)
    const float*  __restrict__ scores,  // [N_CLS, N_BOX]
    float*        __restrict__ out,     // float32 output
    int out_size)
{
    const int c   = blockIdx.x;
    const int tid = threadIdx.x;

    __shared__ unsigned long long keys[N_BOX];
    __shared__ float4 b4s[N_BOX];
    __shared__ float  ars[N_BOX];
    __shared__ unsigned char keepb[N_BOX];
    __shared__ int    res_s[MAX_OUT];
    __shared__ int    s_cut;
    __shared__ int    s_next[3];          // rotating next-live-index slots

    // Zero this block's slice of the output; block 0 scatters only after all
    // blocks arrive, so ordering is covered by the fence + arrival counter.
    {
        int i = c * THREADS + tid;
        if (i < out_size) out[i] = 0.0f;
    }

    // ---- composite keys: ascending == (score desc, index asc) ----
    const float* sc = scores + (size_t)c * N_BOX;
    for (int t = tid; t < N_BOX; t += THREADS) {
        unsigned int bits = __float_as_uint(sc[t]);
        keys[t] = ((unsigned long long)(~bits) << 32) | (unsigned int)t;
    }
    if (tid == 0) {
        s_cut = 0;
        s_next[0] = LIVE_INF; s_next[1] = LIVE_INF; s_next[2] = LIVE_INF;
    }
    __syncthreads();

    // ---- bitonic sort ascending (keys unique: index in low bits) ----
    for (int k = 2; k <= N_BOX; k <<= 1) {
        for (int j = k >> 1; j > 0; j >>= 1) {
            for (int t = tid; t < N_BOX; t += THREADS) {
                int ixj = t ^ j;
                if (ixj > t) {
                    bool up = ((t & k) == 0);
                    unsigned long long a = keys[t], b = keys[ixj];
                    if ((a > b) == up) { keys[t] = b; keys[ixj] = a; }
                }
            }
            __syncthreads();
        }
    }

    // ---- cutoff = #scores > 0.5 (a prefix of the sorted order) ----
    for (int t = tid; t < N_BOX; t += THREADS) {
        float s  = __uint_as_float(~(unsigned int)(keys[t] >> 32));
        bool kt  = (s > 0.5f);
        bool kt1 = false;
        if (t < N_BOX - 1) {
            float s1 = __uint_as_float(~(unsigned int)(keys[t + 1] >> 32));
            kt1 = (s1 > 0.5f);
        }
        if (kt && !kt1) s_cut = t + 1;
        if (t == N_BOX - 1 && kt) s_cut = N_BOX;
    }
    __syncthreads();
    const int cutoff = s_cut;

    // ---- gather boxes (sorted order); all prefix items start live ----
    for (int t = tid; t < cutoff; t += THREADS) {
        int o = (int)(keys[t] & 0xFFFFFFFFull);
        float4 b = boxes[o];               // (y1,x1,y2,x2)
        b4s[t] = b;
        ars[t] = __fmul_rn(__fsub_rn(b.z, b.x), __fsub_rn(b.w, b.y));
        keepb[t] = 1;
    }
    __syncthreads();

    // ---- greedy NMS: ONE barrier per KEPT item. Each pass suppresses the
    // tail against box i and simultaneously finds the next live index via
    // per-thread min -> warp REDUX.MIN -> per-warp atomicMin into a rotating
    // 3-slot cell (slot r%3 is reset at iteration r-1... two barriers before
    // its next atomics, so the reset is ordered). Visits kept items only. ----
    int rank = 0;                 // uniform: identical control flow everywhere
    if (cutoff > 0) {
        int i = 0;                // position 0 = top score > 0.5 => kept
        int it = 0;
        while (true) {
            if (tid == 0) res_s[rank] = (int)(keys[i] & 0xFFFFFFFFull);
            rank++;
            if (rank >= MAX_OUT) break;

            const float4 bi = b4s[i];
            const float  ai = ars[i];
            unsigned int myMin = LIVE_INF;
            for (int j = i + 1 + tid; j < cutoff; j += THREADS) {
                if (keepb[j]) {
                    float4 bj = b4s[j];
                    float ih = fmaxf(__fsub_rn(fminf(bi.z, bj.z),
                                               fmaxf(bi.x, bj.x)), 0.0f);
                    float iw = fmaxf(__fsub_rn(fminf(bi.w, bj.w),
                                               fmaxf(bi.y, bj.y)), 0.0f);
                    float inter = __fmul_rn(ih, iw);
                    float uni   = __fsub_rn(__fadd_rn(ai, ars[j]), inter);
                    // NaN (0/0) > 0.5 is false, matching the reference.
                    if (__fdiv_rn(inter, uni) > 0.5f) {
                        keepb[j] = 0;
                    } else if (myMin == LIVE_INF) {
                        myMin = (unsigned int)j;   // j ascends per thread
                    }
                }
            }
            unsigned int wmin = __reduce_min_sync(0xFFFFFFFFu, myMin);
            const int slot = it - (it / 3) * 3;
            if ((tid & 31) == 0 && wmin != LIVE_INF)
                atomicMin(&s_next[slot], (int)wmin);
            // Reset the slot for iteration it+2: its next atomics happen
            // after the barrier of iteration it+1 -> ordered.
            const int nslot = (it + 2) - ((it + 2) / 3) * 3;
            if (tid == 0 && it >= 1) s_next[nslot] = LIVE_INF;
            __syncthreads();

            int ni = s_next[slot];
            if (ni == LIVE_INF) break;     // no live candidates remain
            i = ni;
            ++it;
        }
    }
    __syncthreads();

    // ---- publish per-class results; release; arrive ----
    for (int t = tid; t < rank; t += THREADS)
        g_res[c * MAX_OUT + t] = res_s[t];
    if (tid == 0) g_cnt[c] = rank;
    __threadfence();
    __syncthreads();
    if (tid == 0) atomicAdd(&g_done, 1);

    // ---- block 0: wait for all classes, scatter compacted float rows ----
    if (c == 0) {
        if (tid == 0) {
            while (atomicAdd(&g_done, 0) < N_CLS) __nanosleep(100);
        }
        __syncthreads();
        __threadfence();

        __shared__ int s_cnt[N_CLS];
        __shared__ int offs[N_CLS];
        if (tid < N_CLS) s_cnt[tid] = g_cnt[tid];   // parallel loads
        __syncthreads();
        if (tid == 0) {
            int acc = 0;
            #pragma unroll 8
            for (int cc = 0; cc < N_CLS; ++cc) { offs[cc] = acc; acc += s_cnt[cc]; }
        }
        __syncthreads();

        for (int e = tid; e < N_CLS * MAX_OUT; e += THREADS) {
            int cc = e / MAX_OUT;
            int k  = e - cc * MAX_OUT;
            if (k < s_cnt[cc]) {
                int p = offs[cc] + k;
                out[3 * p + 0] = 0.0f;            // batch index (B == 1)
                out[3 * p + 1] = (float)cc;
                out[3 * p + 2] = (float)g_res[e];
            }
        }
        __syncthreads();
        if (tid == 0) { __threadfence(); g_done = 0; }   // reset for replay
    }
}

extern "C" void kernel_launch(void* const* d_in, const int* in_sizes, int n_in,
                              void* d_out, int out_size)
{
    const float* boxes  = (const float*)d_in[0];
    const float* scores = (const float*)(n_in > 1 ? d_in[1] : d_in[0]);
    if (n_in > 1 && in_sizes[0] > in_sizes[1]) {   // clearly reversed
        const float* t = boxes; boxes = scores; scores = t;
    }

    nms_fused<<<N_CLS, THREADS>>>((const float4*)boxes, scores,
                                  (float*)d_out, out_size);
}